// round 6
// baseline (speedup 1.0000x reference)
#include <cuda_runtime.h>
#include <cuda_bf16.h>
#include <math.h>

// ---------------------------------------------------------------------------
// TwoLayerGAT on GB300 (sm_103a).
//   CSR build (once; same graph both layers):
//     zero+detect -> count -> scan -> scatter
//   Layer 1: GEMM1 (+fused per-head scores) -> agg1 (softmax-agg, +b1, relu)
//   Layer 2: GEMM2 (+fused scores)          -> agg2 (softmax-agg, +b2) -> out
// All launches graph-capturable; scratch in __device__ globals.
// ---------------------------------------------------------------------------

#define MAXN 50176          // >= 50000
#define MAXET 860160        // >= 800000 + 50000

__device__ float g_h1[MAXN * 128];
__device__ float g_t1[MAXN * 128];
__device__ float g_h2[MAXN * 64];
__device__ float g_s1[MAXN * 4];
__device__ float g_d1[MAXN * 4];
__device__ float g_s2[MAXN];
__device__ float g_d2[MAXN];
__device__ int   g_counts[MAXN + 1];
__device__ int   g_rowptr[MAXN + 1];
__device__ int   g_cursor[MAXN];
__device__ int   g_csr[MAXET];
__device__ int   g_is64;

// ---------------------------------------------------------------------------
// Thread 0 additionally detects the edge dtype. If the buffer holds int32
// ids (< N), reading pairs as int64 gives lo | (hi<<32) with hi a ~uniform
// node id; P(8 sampled his all 0) ~ N^-8 — negligible.
__global__ void k_zero_and_detect(const void* ei, int N) {
    int i = blockIdx.x * blockDim.x + threadIdx.x;
    if (i <= N) g_counts[i] = 0;
    if (i == 0) {
        const long long* p = (const long long*)ei;
        int ok = 1;
        #pragma unroll
        for (int j = 0; j < 8; j++) {
            long long v = p[j];
            if (v < 0 || v >= (long long)N) ok = 0;
        }
        g_is64 = ok;
    }
}

// Both dtype variants of edge kernels are launched every time; each checks
// the device flag once (uniform branch) and the wrong variant exits.

template <bool IS64>
__device__ __forceinline__ int edge_dst(const void* ei, int i, long long E) {
    if (IS64) return (int)__ldg(&((const long long*)ei)[E + i]);
    else      return __ldg(&((const int*)ei)[(int)E + i]);
}
template <bool IS64>
__device__ __forceinline__ int edge_src(const void* ei, int i) {
    if (IS64) return (int)__ldg(&((const long long*)ei)[i]);
    else      return __ldg(&((const int*)ei)[i]);
}

template <bool IS64>
__global__ void k_count(const void* ei, long long E, int N, int Etot) {
    if ((g_is64 != 0) != IS64) return;
    int i = blockIdx.x * blockDim.x + threadIdx.x;
    if (i >= Etot) return;
    int dst;
    if (i < (int)E) dst = edge_dst<IS64>(ei, i, E);
    else            dst = i - (int)E;   // self-loop
    atomicAdd(&g_counts[dst], 1);
}

// Single-block scan: counts -> rowptr (exclusive at i, total at N) + cursor.
__global__ void k_scan(int N) {
    __shared__ int sm[1024];
    int t = threadIdx.x;
    int CH = (N + 1023) / 1024;
    int b = t * CH;
    int e = b + CH; if (e > N) e = N;
    int local = 0;
    for (int i = b; i < e; i++) local += g_counts[i];
    sm[t] = local;
    __syncthreads();
    for (int d = 1; d < 1024; d <<= 1) {
        int v = (t >= d) ? sm[t - d] : 0;
        __syncthreads();
        sm[t] += v;
        __syncthreads();
    }
    int run = sm[t] - local;   // exclusive prefix across threads
    for (int i = b; i < e; i++) {
        g_cursor[i] = run;
        run += g_counts[i];
        g_rowptr[i + 1] = run;
    }
    if (t == 0) g_rowptr[0] = 0;
}

template <bool IS64>
__global__ void k_scatter(const void* ei, long long E, int N, int Etot) {
    if ((g_is64 != 0) != IS64) return;
    int i = blockIdx.x * blockDim.x + threadIdx.x;
    if (i >= Etot) return;
    int src, dst;
    if (i < (int)E) {
        src = edge_src<IS64>(ei, i);
        dst = edge_dst<IS64>(ei, i, E);
    } else {
        src = dst = i - (int)E;
    }
    int pos = atomicAdd(&g_cursor[dst], 1);
    g_csr[pos] = src;
}

// ---------------------------------------------------------------------------
// GEMM: C[M,NCOLS] = A[M,128] @ W[128,NCOLS], 64-row blocks, K tiled by 64.
// Fused epilogue: per-row attention scores vs a_src/a_dst.
//   HEADS=4 (NCOLS=128): head h spans cols [32h,32h+32) = lanes 8h..8h+7,
//     8-lane shuffle reduce, write g_s1/g_d1[row*4+h].
//   HEADS=1 (NCOLS=64): full-warp reduce, write g_s2/g_d2[row].
template <int NCOLS, int HEADS>
__global__ void __launch_bounds__(256) k_gemm128(
    const float* __restrict__ A, const float* __restrict__ W,
    const float* __restrict__ a_s, const float* __restrict__ a_d,
    float* __restrict__ C, float* __restrict__ Sarr, float* __restrict__ Darr,
    int M)
{
    constexpr int KT = 64, ROWS = 64;
    constexpr int CPL = NCOLS / 32;            // columns per lane
    __shared__ float Ws[KT * NCOLS];
    __shared__ float As[ROWS * KT];
    int t = threadIdx.x, warp = t >> 5, lane = t & 31;
    int row0 = blockIdx.x * ROWS;

    float acc[8 * CPL];
    #pragma unroll
    for (int i = 0; i < 8 * CPL; i++) acc[i] = 0.f;

    for (int kt = 0; kt < 2; kt++) {
        for (int i = t; i < KT * NCOLS / 4; i += 256)
            *(float4*)&Ws[i * 4] = *(const float4*)&W[kt * KT * NCOLS + i * 4];
        for (int i = t; i < ROWS * KT / 4; i += 256) {
            int idx = i * 4;
            int r = idx / KT, k = idx % KT;
            int row = row0 + r;
            float4 v = make_float4(0.f, 0.f, 0.f, 0.f);
            if (row < M) v = *(const float4*)&A[row * 128 + kt * KT + k];
            *(float4*)&As[idx] = v;
        }
        __syncthreads();

        #pragma unroll 4
        for (int k = 0; k < KT; k++) {
            float wv[CPL];
            #pragma unroll
            for (int j = 0; j < CPL; j++) wv[j] = Ws[k * NCOLS + lane * CPL + j];
            #pragma unroll
            for (int rr = 0; rr < 8; rr++) {
                float xv = As[(warp * 8 + rr) * KT + k];
                #pragma unroll
                for (int j = 0; j < CPL; j++)
                    acc[rr * CPL + j] = fmaf(xv, wv[j], acc[rr * CPL + j]);
            }
        }
        __syncthreads();
    }

    float avs[CPL], avd[CPL];
    #pragma unroll
    for (int j = 0; j < CPL; j++) {
        avs[j] = a_s[lane * CPL + j];
        avd[j] = a_d[lane * CPL + j];
    }

    #pragma unroll
    for (int rr = 0; rr < 8; rr++) {
        int row = row0 + warp * 8 + rr;
        bool live = row < M;
        if (live) {
            #pragma unroll
            for (int j = 0; j < CPL; j++)
                C[row * NCOLS + lane * CPL + j] = acc[rr * CPL + j];
        }
        float ps = 0.f, pd = 0.f;
        #pragma unroll
        for (int j = 0; j < CPL; j++) {
            ps = fmaf(acc[rr * CPL + j], avs[j], ps);
            pd = fmaf(acc[rr * CPL + j], avd[j], pd);
        }
        if (HEADS == 4) {
            #pragma unroll
            for (int m = 4; m >= 1; m >>= 1) {
                ps += __shfl_xor_sync(0xffffffff, ps, m);
                pd += __shfl_xor_sync(0xffffffff, pd, m);
            }
            if (live && (lane & 7) == 0) {
                int hh = lane >> 3;
                Sarr[row * 4 + hh] = ps;
                Darr[row * 4 + hh] = pd;
            }
        } else {
            #pragma unroll
            for (int m = 16; m >= 1; m >>= 1) {
                ps += __shfl_xor_sync(0xffffffff, ps, m);
                pd += __shfl_xor_sync(0xffffffff, pd, m);
            }
            if (live && lane == 0) {
                Sarr[row] = ps;
                Darr[row] = pd;
            }
        }
    }
}

// ---------------------------------------------------------------------------
// agg1: warp per dst node; lane owns 4 channels; head = lane>>3.
// Shift-free softmax (logits bounded ~|10|; fp32 exp safe; ~ulp match).
// 2-way unrolled with independent accumulator pairs: MLP ~4 on the
// csr->score/h-row chains, halved FMA chain depth.
__global__ void k_agg1(const float* __restrict__ h1,
                       const float* __restrict__ b1, int N)
{
    int wid = (blockIdx.x * blockDim.x + threadIdx.x) >> 5;
    int lane = threadIdx.x & 31;
    if (wid >= N) return;
    int hh = lane >> 3;
    float dd = g_d1[wid * 4 + hh];
    int beg = g_rowptr[wid], end = g_rowptr[wid + 1];

    float4 acc0 = make_float4(0.f, 0.f, 0.f, 0.f);
    float4 acc1 = make_float4(0.f, 0.f, 0.f, 0.f);
    float dsum0 = 0.f, dsum1 = 0.f;

    int k = beg;
    for (; k + 1 < end; k += 2) {
        int sa = g_csr[k];
        int sb = g_csr[k + 1];
        float ea = g_s1[sa * 4 + hh] + dd;
        float eb = g_s1[sb * 4 + hh] + dd;
        ea = ea > 0.f ? ea : 0.2f * ea;
        eb = eb > 0.f ? eb : 0.2f * eb;
        float wa = __expf(ea);
        float wb = __expf(eb);
        float4 ha = *(const float4*)&h1[sa * 128 + lane * 4];
        float4 hb = *(const float4*)&h1[sb * 128 + lane * 4];
        dsum0 += wa;
        dsum1 += wb;
        acc0.x = fmaf(wa, ha.x, acc0.x);  acc1.x = fmaf(wb, hb.x, acc1.x);
        acc0.y = fmaf(wa, ha.y, acc0.y);  acc1.y = fmaf(wb, hb.y, acc1.y);
        acc0.z = fmaf(wa, ha.z, acc0.z);  acc1.z = fmaf(wb, hb.z, acc1.z);
        acc0.w = fmaf(wa, ha.w, acc0.w);  acc1.w = fmaf(wb, hb.w, acc1.w);
    }
    if (k < end) {
        int sa = g_csr[k];
        float ea = g_s1[sa * 4 + hh] + dd;
        ea = ea > 0.f ? ea : 0.2f * ea;
        float wa = __expf(ea);
        float4 ha = *(const float4*)&h1[sa * 128 + lane * 4];
        dsum0 += wa;
        acc0.x = fmaf(wa, ha.x, acc0.x);
        acc0.y = fmaf(wa, ha.y, acc0.y);
        acc0.z = fmaf(wa, ha.z, acc0.z);
        acc0.w = fmaf(wa, ha.w, acc0.w);
    }

    float inv = 1.f / (dsum0 + dsum1);
    float4 bb = *(const float4*)&b1[lane * 4];
    float4 o;
    o.x = fmaxf(fmaf(acc0.x + acc1.x, inv, bb.x), 0.f);
    o.y = fmaxf(fmaf(acc0.y + acc1.y, inv, bb.y), 0.f);
    o.z = fmaxf(fmaf(acc0.z + acc1.z, inv, bb.z), 0.f);
    o.w = fmaxf(fmaf(acc0.w + acc1.w, inv, bb.w), 0.f);
    *(float4*)&g_t1[wid * 128 + lane * 4] = o;
}

// agg2: warp per dst node; lane owns 2 channels; single head.
__global__ void k_agg2(const float* __restrict__ b2,
                       float* __restrict__ out, int N)
{
    int wid = (blockIdx.x * blockDim.x + threadIdx.x) >> 5;
    int lane = threadIdx.x & 31;
    if (wid >= N) return;
    float dd = g_d2[wid];
    int beg = g_rowptr[wid], end = g_rowptr[wid + 1];

    float2 acc0 = make_float2(0.f, 0.f);
    float2 acc1 = make_float2(0.f, 0.f);
    float dsum0 = 0.f, dsum1 = 0.f;

    int k = beg;
    for (; k + 1 < end; k += 2) {
        int sa = g_csr[k];
        int sb = g_csr[k + 1];
        float ea = g_s2[sa] + dd;
        float eb = g_s2[sb] + dd;
        ea = ea > 0.f ? ea : 0.2f * ea;
        eb = eb > 0.f ? eb : 0.2f * eb;
        float wa = __expf(ea);
        float wb = __expf(eb);
        float2 ha = *(const float2*)&g_h2[sa * 64 + lane * 2];
        float2 hb = *(const float2*)&g_h2[sb * 64 + lane * 2];
        dsum0 += wa;
        dsum1 += wb;
        acc0.x = fmaf(wa, ha.x, acc0.x);  acc1.x = fmaf(wb, hb.x, acc1.x);
        acc0.y = fmaf(wa, ha.y, acc0.y);  acc1.y = fmaf(wb, hb.y, acc1.y);
    }
    if (k < end) {
        int sa = g_csr[k];
        float ea = g_s2[sa] + dd;
        ea = ea > 0.f ? ea : 0.2f * ea;
        float wa = __expf(ea);
        float2 ha = *(const float2*)&g_h2[sa * 64 + lane * 2];
        dsum0 += wa;
        acc0.x = fmaf(wa, ha.x, acc0.x);
        acc0.y = fmaf(wa, ha.y, acc0.y);
    }

    float inv = 1.f / (dsum0 + dsum1);
    float2 bb = *(const float2*)&b2[lane * 2];
    float2 o;
    o.x = fmaf(acc0.x + acc1.x, inv, bb.x);
    o.y = fmaf(acc0.y + acc1.y, inv, bb.y);
    *(float2*)&out[wid * 64 + lane * 2] = o;
}

// ---------------------------------------------------------------------------
extern "C" void kernel_launch(void* const* d_in, const int* in_sizes, int n_in,
                              void* d_out, int out_size)
{
    const float* x   = (const float*)d_in[0];
    const void*  ei  = d_in[1];
    // d_in[2] = drpt, unused at inference
    const float* W1  = (const float*)d_in[3];
    const float* a1s = (const float*)d_in[4];
    const float* a1d = (const float*)d_in[5];
    const float* b1  = (const float*)d_in[6];
    const float* W2  = (const float*)d_in[7];
    const float* a2s = (const float*)d_in[8];
    const float* a2d = (const float*)d_in[9];
    const float* b2  = (const float*)d_in[10];

    int N = in_sizes[0] / 128;
    long long E = in_sizes[1] / 2;
    int Etot = (int)E + N;

    float* h1p; cudaGetSymbolAddress((void**)&h1p, g_h1);
    float* t1p; cudaGetSymbolAddress((void**)&t1p, g_t1);
    float* h2p; cudaGetSymbolAddress((void**)&h2p, g_h2);
    float* s1p; cudaGetSymbolAddress((void**)&s1p, g_s1);
    float* d1p; cudaGetSymbolAddress((void**)&d1p, g_d1);
    float* s2p; cudaGetSymbolAddress((void**)&s2p, g_s2);
    float* d2p; cudaGetSymbolAddress((void**)&d2p, g_d2);

    int egrid = (Etot + 255) / 256;

    // ---- CSR build ----
    k_zero_and_detect<<<(N + 511) / 512, 512>>>(ei, N);
    k_count<true ><<<egrid, 256>>>(ei, E, N, Etot);
    k_count<false><<<egrid, 256>>>(ei, E, N, Etot);
    k_scan<<<1, 1024>>>(N);
    k_scatter<true ><<<egrid, 256>>>(ei, E, N, Etot);
    k_scatter<false><<<egrid, 256>>>(ei, E, N, Etot);

    // ---- layer 1 ----
    k_gemm128<128, 4><<<(N + 63) / 64, 256>>>(x, W1, a1s, a1d, h1p, s1p, d1p, N);
    k_agg1<<<(N + 7) / 8, 256>>>(h1p, b1, N);

    // ---- layer 2 ----
    k_gemm128<64, 1><<<(N + 63) / 64, 256>>>(t1p, W2, a2s, a2d, h2p, s2p, d2p, N);
    k_agg2<<<(N + 7) / 8, 256>>>(b2, (float*)d_out, N);
}

// round 10
// speedup vs baseline: 1.3248x; 1.3248x over previous
#include <cuda_runtime.h>
#include <cuda_bf16.h>
#include <math.h>

// ---------------------------------------------------------------------------
// TwoLayerGAT on GB300 (sm_103a).
//   CSR build: zero+detect -> count -> 3-phase parallel scan -> scatter
//   Layer 1: GEMM1 (+fused per-head scores) -> agg1 (softmax-agg, +b1, relu)
//   Layer 2: GEMM2 (+fused scores)          -> agg2 (softmax-agg, +b2) -> out
// All launches graph-capturable; scratch in __device__ globals.
// ---------------------------------------------------------------------------

#define MAXN 50176          // >= 50000
#define MAXET 860160        // >= 800000 + 50000
#define SCAN_CH 256         // elements per scan block
#define SCAN_NBMAX 256      // ceil(MAXN/SCAN_CH) = 196 <= 256

__device__ float g_h1[MAXN * 128];
__device__ float g_t1[MAXN * 128];
__device__ float g_h2[MAXN * 64];
__device__ float g_s1[MAXN * 4];
__device__ float g_d1[MAXN * 4];
__device__ float g_s2[MAXN];
__device__ float g_d2[MAXN];
__device__ int   g_counts[MAXN + 1];
__device__ int   g_rowptr[MAXN + 1];
__device__ int   g_cursor[MAXN];
__device__ int   g_csr[MAXET];
__device__ int   g_bsum[SCAN_NBMAX];
__device__ int   g_boff[SCAN_NBMAX];
__device__ int   g_is64;

// ---------------------------------------------------------------------------
// Thread 0 additionally detects the edge dtype. If the buffer holds int32
// ids (< N), reading pairs as int64 gives lo | (hi<<32) with hi a ~uniform
// node id; P(8 sampled his all 0) ~ N^-8 — negligible.
__global__ void k_zero_and_detect(const void* ei, int N) {
    int i = blockIdx.x * blockDim.x + threadIdx.x;
    if (i <= N) g_counts[i] = 0;
    if (i == 0) {
        const long long* p = (const long long*)ei;
        int ok = 1;
        #pragma unroll
        for (int j = 0; j < 8; j++) {
            long long v = p[j];
            if (v < 0 || v >= (long long)N) ok = 0;
        }
        g_is64 = ok;
    }
}

__device__ __forceinline__ int edge_dst(const void* ei, int i, long long E) {
    if (g_is64) return (int)__ldg(&((const long long*)ei)[E + i]);
    else        return __ldg(&((const int*)ei)[(int)E + i]);
}
__device__ __forceinline__ int edge_src(const void* ei, int i) {
    if (g_is64) return (int)__ldg(&((const long long*)ei)[i]);
    else        return __ldg(&((const int*)ei)[i]);
}

__global__ void k_count(const void* ei, long long E, int N, int Etot) {
    int i = blockIdx.x * blockDim.x + threadIdx.x;
    if (i >= Etot) return;
    int dst;
    if (i < (int)E) dst = edge_dst(ei, i, E);
    else            dst = i - (int)E;   // self-loop
    atomicAdd(&g_counts[dst], 1);
}

// ---------------------------------------------------------------------------
// 3-phase parallel scan over g_counts[0..N) -> g_rowptr (exclusive prefix,
// total at [N]) and g_cursor (exclusive scatter cursors).
// Warp-shuffle inclusive scan of a 256-block.
__device__ __forceinline__ int blk_incl_scan256(int v, int t, int* warpsum) {
    int lane = t & 31, warp = t >> 5;
    #pragma unroll
    for (int d = 1; d < 32; d <<= 1) {
        int x = __shfl_up_sync(0xffffffff, v, d);
        if (lane >= d) v += x;
    }
    if (lane == 31) warpsum[warp] = v;
    __syncthreads();
    if (warp == 0) {
        int w = (lane < 8) ? warpsum[lane] : 0;
        #pragma unroll
        for (int d = 1; d < 8; d <<= 1) {
            int x = __shfl_up_sync(0xffffffff, w, d);
            if (lane >= d) w += x;
        }
        if (lane < 8) warpsum[lane] = w;
    }
    __syncthreads();
    return v + (warp > 0 ? warpsum[warp - 1] : 0);
}

// Phase 1: per-block inclusive scan of a 256-chunk; block totals -> g_bsum.
__global__ void k_scan_blk(int N) {
    __shared__ int wsum[8];
    int b = blockIdx.x, t = threadIdx.x;
    int i = b * SCAN_CH + t;
    int v = (i < N) ? g_counts[i] : 0;
    int incl = blk_incl_scan256(v, t, wsum);
    if (i < N) g_cursor[i] = incl;        // temp: block-local inclusive scan
    if (t == SCAN_CH - 1) g_bsum[b] = incl;
}

// Phase 2: one 256-thread block exclusive-scans the <=256 block totals.
__global__ void k_scan_top(int nb) {
    __shared__ int wsum[8];
    int t = threadIdx.x;
    int v = (t < nb) ? g_bsum[t] : 0;
    int incl = blk_incl_scan256(v, t, wsum);
    g_boff[t] = incl - v;                 // exclusive
}

// Phase 3: add block offsets; emit rowptr (incl at i+1) + cursor (excl at i).
__global__ void k_scan_add(int N) {
    int b = blockIdx.x, t = threadIdx.x;
    int i = b * SCAN_CH + t;
    if (i >= N) return;
    int incl = g_cursor[i] + g_boff[b];
    g_rowptr[i + 1] = incl;
    g_cursor[i] = incl - g_counts[i];
    if (i == 0) g_rowptr[0] = 0;
}

__global__ void k_scatter(const void* ei, long long E, int N, int Etot) {
    int i = blockIdx.x * blockDim.x + threadIdx.x;
    if (i >= Etot) return;
    int src, dst;
    if (i < (int)E) {
        src = edge_src(ei, i);
        dst = edge_dst(ei, i, E);
    } else {
        src = dst = i - (int)E;
    }
    int pos = atomicAdd(&g_cursor[dst], 1);
    g_csr[pos] = src;
}

// ---------------------------------------------------------------------------
// GEMM: C[M,NCOLS] = A[M,128] @ W[128,NCOLS], 64-row blocks, K tiled by 64.
// Fused epilogue (vectorized stores): per-row attention scores vs a_src/a_dst.
template <int NCOLS, int HEADS>
__global__ void __launch_bounds__(256) k_gemm128(
    const float* __restrict__ A, const float* __restrict__ W,
    const float* __restrict__ a_s, const float* __restrict__ a_d,
    float* __restrict__ C, float* __restrict__ Sarr, float* __restrict__ Darr,
    int M)
{
    constexpr int KT = 64, ROWS = 64;
    constexpr int CPL = NCOLS / 32;            // columns per lane (4 or 2)
    __shared__ float Ws[KT * NCOLS];
    __shared__ float As[ROWS * KT];
    int t = threadIdx.x, warp = t >> 5, lane = t & 31;
    int row0 = blockIdx.x * ROWS;

    float acc[8 * CPL];
    #pragma unroll
    for (int i = 0; i < 8 * CPL; i++) acc[i] = 0.f;

    for (int kt = 0; kt < 2; kt++) {
        for (int i = t; i < KT * NCOLS / 4; i += 256)
            *(float4*)&Ws[i * 4] = *(const float4*)&W[kt * KT * NCOLS + i * 4];
        for (int i = t; i < ROWS * KT / 4; i += 256) {
            int idx = i * 4;
            int r = idx / KT, k = idx % KT;
            int row = row0 + r;
            float4 v = make_float4(0.f, 0.f, 0.f, 0.f);
            if (row < M) v = *(const float4*)&A[row * 128 + kt * KT + k];
            *(float4*)&As[idx] = v;
        }
        __syncthreads();

        #pragma unroll 4
        for (int k = 0; k < KT; k++) {
            float wv[CPL];
            #pragma unroll
            for (int j = 0; j < CPL; j++) wv[j] = Ws[k * NCOLS + lane * CPL + j];
            #pragma unroll
            for (int rr = 0; rr < 8; rr++) {
                float xv = As[(warp * 8 + rr) * KT + k];
                #pragma unroll
                for (int j = 0; j < CPL; j++)
                    acc[rr * CPL + j] = fmaf(xv, wv[j], acc[rr * CPL + j]);
            }
        }
        __syncthreads();
    }

    // attention-vector slices this lane owns (vector loads: contiguous CPL)
    float avs[CPL], avd[CPL];
    if (CPL == 4) {
        *(float4*)avs = *(const float4*)&a_s[lane * 4];
        *(float4*)avd = *(const float4*)&a_d[lane * 4];
    } else {
        *(float2*)avs = *(const float2*)&a_s[lane * 2];
        *(float2*)avd = *(const float2*)&a_d[lane * 2];
    }

    #pragma unroll
    for (int rr = 0; rr < 8; rr++) {
        int row = row0 + warp * 8 + rr;
        bool live = row < M;
        if (live) {
            if (CPL == 4)
                *(float4*)&C[row * NCOLS + lane * 4] = *(float4*)&acc[rr * 4];
            else
                *(float2*)&C[row * NCOLS + lane * 2] = *(float2*)&acc[rr * 2];
        }
        float ps = 0.f, pd = 0.f;
        #pragma unroll
        for (int j = 0; j < CPL; j++) {
            ps = fmaf(acc[rr * CPL + j], avs[j], ps);
            pd = fmaf(acc[rr * CPL + j], avd[j], pd);
        }
        if (HEADS == 4) {
            #pragma unroll
            for (int m = 4; m >= 1; m >>= 1) {
                ps += __shfl_xor_sync(0xffffffff, ps, m);
                pd += __shfl_xor_sync(0xffffffff, pd, m);
            }
            if (live && (lane & 7) == 0) {
                int hh = lane >> 3;
                Sarr[row * 4 + hh] = ps;
                Darr[row * 4 + hh] = pd;
            }
        } else {
            #pragma unroll
            for (int m = 16; m >= 1; m >>= 1) {
                ps += __shfl_xor_sync(0xffffffff, ps, m);
                pd += __shfl_xor_sync(0xffffffff, pd, m);
            }
            if (live && lane == 0) {
                Sarr[row] = ps;
                Darr[row] = pd;
            }
        }
    }
}

// ---------------------------------------------------------------------------
// agg1: warp per dst node; lane owns 4 channels; head = lane>>3.
// Shift-free softmax (logits bounded ~|10|; fp32 exp safe; ~ulp match).
// 2-way unrolled with independent accumulator pairs (MLP ~4).
__global__ void k_agg1(const float* __restrict__ h1,
                       const float* __restrict__ b1, int N)
{
    int wid = (blockIdx.x * blockDim.x + threadIdx.x) >> 5;
    int lane = threadIdx.x & 31;
    if (wid >= N) return;
    int hh = lane >> 3;
    float dd = g_d1[wid * 4 + hh];
    int beg = g_rowptr[wid], end = g_rowptr[wid + 1];

    float4 acc0 = make_float4(0.f, 0.f, 0.f, 0.f);
    float4 acc1 = make_float4(0.f, 0.f, 0.f, 0.f);
    float dsum0 = 0.f, dsum1 = 0.f;

    int k = beg;
    for (; k + 1 < end; k += 2) {
        int sa = g_csr[k];
        int sb = g_csr[k + 1];
        float ea = g_s1[sa * 4 + hh] + dd;
        float eb = g_s1[sb * 4 + hh] + dd;
        ea = ea > 0.f ? ea : 0.2f * ea;
        eb = eb > 0.f ? eb : 0.2f * eb;
        float wa = __expf(ea);
        float wb = __expf(eb);
        float4 ha = *(const float4*)&h1[sa * 128 + lane * 4];
        float4 hb = *(const float4*)&h1[sb * 128 + lane * 4];
        dsum0 += wa;
        dsum1 += wb;
        acc0.x = fmaf(wa, ha.x, acc0.x);  acc1.x = fmaf(wb, hb.x, acc1.x);
        acc0.y = fmaf(wa, ha.y, acc0.y);  acc1.y = fmaf(wb, hb.y, acc1.y);
        acc0.z = fmaf(wa, ha.z, acc0.z);  acc1.z = fmaf(wb, hb.z, acc1.z);
        acc0.w = fmaf(wa, ha.w, acc0.w);  acc1.w = fmaf(wb, hb.w, acc1.w);
    }
    if (k < end) {
        int sa = g_csr[k];
        float ea = g_s1[sa * 4 + hh] + dd;
        ea = ea > 0.f ? ea : 0.2f * ea;
        float wa = __expf(ea);
        float4 ha = *(const float4*)&h1[sa * 128 + lane * 4];
        dsum0 += wa;
        acc0.x = fmaf(wa, ha.x, acc0.x);
        acc0.y = fmaf(wa, ha.y, acc0.y);
        acc0.z = fmaf(wa, ha.z, acc0.z);
        acc0.w = fmaf(wa, ha.w, acc0.w);
    }

    float inv = 1.f / (dsum0 + dsum1);
    float4 bb = *(const float4*)&b1[lane * 4];
    float4 o;
    o.x = fmaxf(fmaf(acc0.x + acc1.x, inv, bb.x), 0.f);
    o.y = fmaxf(fmaf(acc0.y + acc1.y, inv, bb.y), 0.f);
    o.z = fmaxf(fmaf(acc0.z + acc1.z, inv, bb.z), 0.f);
    o.w = fmaxf(fmaf(acc0.w + acc1.w, inv, bb.w), 0.f);
    *(float4*)&g_t1[wid * 128 + lane * 4] = o;
}

// agg2: warp per dst node; lane owns 2 channels; single head.
__global__ void k_agg2(const float* __restrict__ b2,
                       float* __restrict__ out, int N)
{
    int wid = (blockIdx.x * blockDim.x + threadIdx.x) >> 5;
    int lane = threadIdx.x & 31;
    if (wid >= N) return;
    float dd = g_d2[wid];
    int beg = g_rowptr[wid], end = g_rowptr[wid + 1];

    float2 acc0 = make_float2(0.f, 0.f);
    float2 acc1 = make_float2(0.f, 0.f);
    float dsum0 = 0.f, dsum1 = 0.f;

    int k = beg;
    for (; k + 1 < end; k += 2) {
        int sa = g_csr[k];
        int sb = g_csr[k + 1];
        float ea = g_s2[sa] + dd;
        float eb = g_s2[sb] + dd;
        ea = ea > 0.f ? ea : 0.2f * ea;
        eb = eb > 0.f ? eb : 0.2f * eb;
        float wa = __expf(ea);
        float wb = __expf(eb);
        float2 ha = *(const float2*)&g_h2[sa * 64 + lane * 2];
        float2 hb = *(const float2*)&g_h2[sb * 64 + lane * 2];
        dsum0 += wa;
        dsum1 += wb;
        acc0.x = fmaf(wa, ha.x, acc0.x);  acc1.x = fmaf(wb, hb.x, acc1.x);
        acc0.y = fmaf(wa, ha.y, acc0.y);  acc1.y = fmaf(wb, hb.y, acc1.y);
    }
    if (k < end) {
        int sa = g_csr[k];
        float ea = g_s2[sa] + dd;
        ea = ea > 0.f ? ea : 0.2f * ea;
        float wa = __expf(ea);
        float2 ha = *(const float2*)&g_h2[sa * 64 + lane * 2];
        dsum0 += wa;
        acc0.x = fmaf(wa, ha.x, acc0.x);
        acc0.y = fmaf(wa, ha.y, acc0.y);
    }

    float inv = 1.f / (dsum0 + dsum1);
    float2 bb = *(const float2*)&b2[lane * 2];
    float2 o;
    o.x = fmaf(acc0.x + acc1.x, inv, bb.x);
    o.y = fmaf(acc0.y + acc1.y, inv, bb.y);
    *(float2*)&out[wid * 64 + lane * 2] = o;
}

// ---------------------------------------------------------------------------
extern "C" void kernel_launch(void* const* d_in, const int* in_sizes, int n_in,
                              void* d_out, int out_size)
{
    const float* x   = (const float*)d_in[0];
    const void*  ei  = d_in[1];
    // d_in[2] = drpt, unused at inference
    const float* W1  = (const float*)d_in[3];
    const float* a1s = (const float*)d_in[4];
    const float* a1d = (const float*)d_in[5];
    const float* b1  = (const float*)d_in[6];
    const float* W2  = (const float*)d_in[7];
    const float* a2s = (const float*)d_in[8];
    const float* a2d = (const float*)d_in[9];
    const float* b2  = (const float*)d_in[10];

    int N = in_sizes[0] / 128;
    long long E = in_sizes[1] / 2;
    int Etot = (int)E + N;

    float* h1p; cudaGetSymbolAddress((void**)&h1p, g_h1);
    float* t1p; cudaGetSymbolAddress((void**)&t1p, g_t1);
    float* h2p; cudaGetSymbolAddress((void**)&h2p, g_h2);
    float* s1p; cudaGetSymbolAddress((void**)&s1p, g_s1);
    float* d1p; cudaGetSymbolAddress((void**)&d1p, g_d1);
    float* s2p; cudaGetSymbolAddress((void**)&s2p, g_s2);
    float* d2p; cudaGetSymbolAddress((void**)&d2p, g_d2);

    int egrid = (Etot + 255) / 256;
    int nb = (N + SCAN_CH - 1) / SCAN_CH;   // scan blocks (196 for N=50k)

    // ---- CSR build ----
    k_zero_and_detect<<<(N + 511) / 512, 512>>>(ei, N);
    k_count<<<egrid, 256>>>(ei, E, N, Etot);
    k_scan_blk<<<nb, SCAN_CH>>>(N);
    k_scan_top<<<1, SCAN_NBMAX>>>(nb);
    k_scan_add<<<nb, SCAN_CH>>>(N);
    k_scatter<<<egrid, 256>>>(ei, E, N, Etot);

    // ---- layer 1 ----
    k_gemm128<128, 4><<<(N + 63) / 64, 256>>>(x, W1, a1s, a1d, h1p, s1p, d1p, N);
    k_agg1<<<(N + 7) / 8, 256>>>(h1p, b1, N);

    // ---- layer 2 ----
    k_gemm128<64, 1><<<(N + 63) / 64, 256>>>(t1p, W2, a2s, a2d, h2p, s2p, d2p, N);
    k_agg2<<<(N + 7) / 8, 256>>>(b2, (float*)d_out, N);
}

// round 13
// speedup vs baseline: 1.3798x; 1.0415x over previous
#include <cuda_runtime.h>
#include <cuda_bf16.h>
#include <cuda_fp16.h>
#include <math.h>

// ---------------------------------------------------------------------------
// TwoLayerGAT on GB300 (sm_103a).
//   CSR build: zero+detect -> count -> 3-phase parallel scan -> scatter
//   Layer 1: GEMM1 (+fused scores, fp16 shadow) -> agg1 (fp16 gather, softmax)
//   Layer 2: GEMM2 (+fused scores, fp16 shadow) -> agg2 -> out
// Gathers read fp16 shadows of h1/h2 (halves L2 gather traffic); all softmax
// weights and accumulation stay fp32.
// ---------------------------------------------------------------------------

#define MAXN 50176          // >= 50000
#define MAXET 860160        // >= 800000 + 50000
#define SCAN_CH 256
#define SCAN_NBMAX 256      // ceil(MAXN/SCAN_CH) = 196 <= 256

__device__ float  g_h1[MAXN * 128];    // (unused when storeC=0; kept as dummy dst)
__device__ __half g_h1h[MAXN * 128];   // fp16 shadow of h1 (gather source)
__device__ float  g_t1[MAXN * 128];
__device__ __half g_h2h[MAXN * 64];    // fp16 shadow of h2 (gather source)
__device__ float  g_s1[MAXN * 4];
__device__ float  g_d1[MAXN * 4];
__device__ float  g_s2[MAXN];
__device__ float  g_d2[MAXN];
__device__ int    g_counts[MAXN + 1];
__device__ int    g_rowptr[MAXN + 1];
__device__ int    g_cursor[MAXN];
__device__ int    g_csr[MAXET];
__device__ int    g_bsum[SCAN_NBMAX];
__device__ int    g_boff[SCAN_NBMAX];
__device__ int    g_is64;

// ---------------------------------------------------------------------------
__global__ void k_zero_and_detect(const void* ei, int N) {
    int i = blockIdx.x * blockDim.x + threadIdx.x;
    if (i <= N) g_counts[i] = 0;
    if (i == 0) {
        const long long* p = (const long long*)ei;
        int ok = 1;
        #pragma unroll
        for (int j = 0; j < 8; j++) {
            long long v = p[j];
            if (v < 0 || v >= (long long)N) ok = 0;
        }
        g_is64 = ok;
    }
}

__device__ __forceinline__ int edge_dst(const void* ei, int i, long long E) {
    if (g_is64) return (int)__ldg(&((const long long*)ei)[E + i]);
    else        return __ldg(&((const int*)ei)[(int)E + i]);
}
__device__ __forceinline__ int edge_src(const void* ei, int i) {
    if (g_is64) return (int)__ldg(&((const long long*)ei)[i]);
    else        return __ldg(&((const int*)ei)[i]);
}

__global__ void k_count(const void* ei, long long E, int N, int Etot) {
    int i = blockIdx.x * blockDim.x + threadIdx.x;
    if (i >= Etot) return;
    int dst;
    if (i < (int)E) dst = edge_dst(ei, i, E);
    else            dst = i - (int)E;   // self-loop
    atomicAdd(&g_counts[dst], 1);
}

// ---------------------------------------------------------------------------
__device__ __forceinline__ int blk_incl_scan256(int v, int t, int* warpsum) {
    int lane = t & 31, warp = t >> 5;
    #pragma unroll
    for (int d = 1; d < 32; d <<= 1) {
        int x = __shfl_up_sync(0xffffffff, v, d);
        if (lane >= d) v += x;
    }
    if (lane == 31) warpsum[warp] = v;
    __syncthreads();
    if (warp == 0) {
        int w = (lane < 8) ? warpsum[lane] : 0;
        #pragma unroll
        for (int d = 1; d < 8; d <<= 1) {
            int x = __shfl_up_sync(0xffffffff, w, d);
            if (lane >= d) w += x;
        }
        if (lane < 8) warpsum[lane] = w;
    }
    __syncthreads();
    return v + (warp > 0 ? warpsum[warp - 1] : 0);
}

__global__ void k_scan_blk(int N) {
    __shared__ int wsum[8];
    int b = blockIdx.x, t = threadIdx.x;
    int i = b * SCAN_CH + t;
    int v = (i < N) ? g_counts[i] : 0;
    int incl = blk_incl_scan256(v, t, wsum);
    if (i < N) g_cursor[i] = incl;        // temp: block-local inclusive scan
    if (t == SCAN_CH - 1) g_bsum[b] = incl;
}

__global__ void k_scan_top(int nb) {
    __shared__ int wsum[8];
    int t = threadIdx.x;
    int v = (t < nb) ? g_bsum[t] : 0;
    int incl = blk_incl_scan256(v, t, wsum);
    g_boff[t] = incl - v;                 // exclusive
}

__global__ void k_scan_add(int N) {
    int b = blockIdx.x, t = threadIdx.x;
    int i = b * SCAN_CH + t;
    if (i >= N) return;
    int incl = g_cursor[i] + g_boff[b];
    g_rowptr[i + 1] = incl;
    g_cursor[i] = incl - g_counts[i];
    if (i == 0) g_rowptr[0] = 0;
}

__global__ void k_scatter(const void* ei, long long E, int N, int Etot) {
    int i = blockIdx.x * blockDim.x + threadIdx.x;
    if (i >= Etot) return;
    int src, dst;
    if (i < (int)E) {
        src = edge_src(ei, i);
        dst = edge_dst(ei, i, E);
    } else {
        src = dst = i - (int)E;
    }
    int pos = atomicAdd(&g_cursor[dst], 1);
    g_csr[pos] = src;
}

// ---------------------------------------------------------------------------
// GEMM: C[M,NCOLS] = A[M,128] @ W[128,NCOLS], 64-row blocks, K tiled by 64.
// Epilogue: optional fp32 C store + fp16 shadow store + fused scores.
template <int NCOLS, int HEADS>
__global__ void __launch_bounds__(256) k_gemm128(
    const float* __restrict__ A, const float* __restrict__ W,
    const float* __restrict__ a_s, const float* __restrict__ a_d,
    float* __restrict__ C, __half* __restrict__ Ch,
    float* __restrict__ Sarr, float* __restrict__ Darr,
    int M, int storeC)
{
    constexpr int KT = 64, ROWS = 64;
    constexpr int CPL = NCOLS / 32;            // columns per lane (4 or 2)
    __shared__ float Ws[KT * NCOLS];
    __shared__ float As[ROWS * KT];
    int t = threadIdx.x, warp = t >> 5, lane = t & 31;
    int row0 = blockIdx.x * ROWS;

    float acc[8 * CPL];
    #pragma unroll
    for (int i = 0; i < 8 * CPL; i++) acc[i] = 0.f;

    for (int kt = 0; kt < 2; kt++) {
        for (int i = t; i < KT * NCOLS / 4; i += 256)
            *(float4*)&Ws[i * 4] = *(const float4*)&W[kt * KT * NCOLS + i * 4];
        for (int i = t; i < ROWS * KT / 4; i += 256) {
            int idx = i * 4;
            int r = idx / KT, k = idx % KT;
            int row = row0 + r;
            float4 v = make_float4(0.f, 0.f, 0.f, 0.f);
            if (row < M) v = *(const float4*)&A[row * 128 + kt * KT + k];
            *(float4*)&As[idx] = v;
        }
        __syncthreads();

        #pragma unroll 4
        for (int k = 0; k < KT; k++) {
            float wv[CPL];
            #pragma unroll
            for (int j = 0; j < CPL; j++) wv[j] = Ws[k * NCOLS + lane * CPL + j];
            #pragma unroll
            for (int rr = 0; rr < 8; rr++) {
                float xv = As[(warp * 8 + rr) * KT + k];
                #pragma unroll
                for (int j = 0; j < CPL; j++)
                    acc[rr * CPL + j] = fmaf(xv, wv[j], acc[rr * CPL + j]);
            }
        }
        __syncthreads();
    }

    float avs[CPL], avd[CPL];
    if (CPL == 4) {
        *(float4*)avs = *(const float4*)&a_s[lane * 4];
        *(float4*)avd = *(const float4*)&a_d[lane * 4];
    } else {
        *(float2*)avs = *(const float2*)&a_s[lane * 2];
        *(float2*)avd = *(const float2*)&a_d[lane * 2];
    }

    #pragma unroll
    for (int rr = 0; rr < 8; rr++) {
        int row = row0 + warp * 8 + rr;
        bool live = row < M;
        if (live) {
            if (storeC) {
                if (CPL == 4)
                    *(float4*)&C[row * NCOLS + lane * 4] = *(float4*)&acc[rr * 4];
                else
                    *(float2*)&C[row * NCOLS + lane * 2] = *(float2*)&acc[rr * 2];
            }
            // fp16 shadow (gather source for agg)
            if (CPL == 4) {
                __half2 p0 = __floats2half2_rn(acc[rr * 4 + 0], acc[rr * 4 + 1]);
                __half2 p1 = __floats2half2_rn(acc[rr * 4 + 2], acc[rr * 4 + 3]);
                *(__half2*)&Ch[row * NCOLS + lane * 4 + 0] = p0;
                *(__half2*)&Ch[row * NCOLS + lane * 4 + 2] = p1;
            } else {
                *(__half2*)&Ch[row * NCOLS + lane * 2] =
                    __floats2half2_rn(acc[rr * 2 + 0], acc[rr * 2 + 1]);
            }
        }
        float ps = 0.f, pd = 0.f;
        #pragma unroll
        for (int j = 0; j < CPL; j++) {
            ps = fmaf(acc[rr * CPL + j], avs[j], ps);
            pd = fmaf(acc[rr * CPL + j], avd[j], pd);
        }
        if (HEADS == 4) {
            #pragma unroll
            for (int m = 4; m >= 1; m >>= 1) {
                ps += __shfl_xor_sync(0xffffffff, ps, m);
                pd += __shfl_xor_sync(0xffffffff, pd, m);
            }
            if (live && (lane & 7) == 0) {
                int hh = lane >> 3;
                Sarr[row * 4 + hh] = ps;
                Darr[row * 4 + hh] = pd;
            }
        } else {
            #pragma unroll
            for (int m = 16; m >= 1; m >>= 1) {
                ps += __shfl_xor_sync(0xffffffff, ps, m);
                pd += __shfl_xor_sync(0xffffffff, pd, m);
            }
            if (live && lane == 0) {
                Sarr[row] = ps;
                Darr[row] = pd;
            }
        }
    }
}

// ---------------------------------------------------------------------------
// agg1: warp per dst node; lane owns 4 channels; head = lane>>3.
// Gathers fp16 shadow rows (8B/lane/edge); weights + accumulation fp32.
__global__ void k_agg1(const float* __restrict__ b1, int N)
{
    int wid = (blockIdx.x * blockDim.x + threadIdx.x) >> 5;
    int lane = threadIdx.x & 31;
    if (wid >= N) return;
    int hh = lane >> 3;
    float dd = g_d1[wid * 4 + hh];
    int beg = g_rowptr[wid], end = g_rowptr[wid + 1];

    float4 acc0 = make_float4(0.f, 0.f, 0.f, 0.f);
    float4 acc1 = make_float4(0.f, 0.f, 0.f, 0.f);
    float dsum0 = 0.f, dsum1 = 0.f;

    int k = beg;
    for (; k + 1 < end; k += 2) {
        int sa = g_csr[k];
        int sb = g_csr[k + 1];
        float ea = g_s1[sa * 4 + hh] + dd;
        float eb = g_s1[sb * 4 + hh] + dd;
        ea = ea > 0.f ? ea : 0.2f * ea;
        eb = eb > 0.f ? eb : 0.2f * eb;
        float wa = __expf(ea);
        float wb = __expf(eb);
        uint2 pa = *(const uint2*)&g_h1h[sa * 128 + lane * 4];
        uint2 pb = *(const uint2*)&g_h1h[sb * 128 + lane * 4];
        float2 a01 = __half22float2(*(__half2*)&pa.x);
        float2 a23 = __half22float2(*(__half2*)&pa.y);
        float2 b01 = __half22float2(*(__half2*)&pb.x);
        float2 b23 = __half22float2(*(__half2*)&pb.y);
        dsum0 += wa;
        dsum1 += wb;
        acc0.x = fmaf(wa, a01.x, acc0.x);  acc1.x = fmaf(wb, b01.x, acc1.x);
        acc0.y = fmaf(wa, a01.y, acc0.y);  acc1.y = fmaf(wb, b01.y, acc1.y);
        acc0.z = fmaf(wa, a23.x, acc0.z);  acc1.z = fmaf(wb, b23.x, acc1.z);
        acc0.w = fmaf(wa, a23.y, acc0.w);  acc1.w = fmaf(wb, b23.y, acc1.w);
    }
    if (k < end) {
        int sa = g_csr[k];
        float ea = g_s1[sa * 4 + hh] + dd;
        ea = ea > 0.f ? ea : 0.2f * ea;
        float wa = __expf(ea);
        uint2 pa = *(const uint2*)&g_h1h[sa * 128 + lane * 4];
        float2 a01 = __half22float2(*(__half2*)&pa.x);
        float2 a23 = __half22float2(*(__half2*)&pa.y);
        dsum0 += wa;
        acc0.x = fmaf(wa, a01.x, acc0.x);
        acc0.y = fmaf(wa, a01.y, acc0.y);
        acc0.z = fmaf(wa, a23.x, acc0.z);
        acc0.w = fmaf(wa, a23.y, acc0.w);
    }

    float inv = 1.f / (dsum0 + dsum1);
    float4 bb = *(const float4*)&b1[lane * 4];
    float4 o;
    o.x = fmaxf(fmaf(acc0.x + acc1.x, inv, bb.x), 0.f);
    o.y = fmaxf(fmaf(acc0.y + acc1.y, inv, bb.y), 0.f);
    o.z = fmaxf(fmaf(acc0.z + acc1.z, inv, bb.z), 0.f);
    o.w = fmaxf(fmaf(acc0.w + acc1.w, inv, bb.w), 0.f);
    *(float4*)&g_t1[wid * 128 + lane * 4] = o;
}

// agg2: warp per dst node; lane owns 2 channels; fp16 gather (4B/lane/edge).
__global__ void k_agg2(const float* __restrict__ b2,
                       float* __restrict__ out, int N)
{
    int wid = (blockIdx.x * blockDim.x + threadIdx.x) >> 5;
    int lane = threadIdx.x & 31;
    if (wid >= N) return;
    float dd = g_d2[wid];
    int beg = g_rowptr[wid], end = g_rowptr[wid + 1];

    float2 acc0 = make_float2(0.f, 0.f);
    float2 acc1 = make_float2(0.f, 0.f);
    float dsum0 = 0.f, dsum1 = 0.f;

    int k = beg;
    for (; k + 1 < end; k += 2) {
        int sa = g_csr[k];
        int sb = g_csr[k + 1];
        float ea = g_s2[sa] + dd;
        float eb = g_s2[sb] + dd;
        ea = ea > 0.f ? ea : 0.2f * ea;
        eb = eb > 0.f ? eb : 0.2f * eb;
        float wa = __expf(ea);
        float wb = __expf(eb);
        float2 ha = __half22float2(*(const __half2*)&g_h2h[sa * 64 + lane * 2]);
        float2 hb = __half22float2(*(const __half2*)&g_h2h[sb * 64 + lane * 2]);
        dsum0 += wa;
        dsum1 += wb;
        acc0.x = fmaf(wa, ha.x, acc0.x);  acc1.x = fmaf(wb, hb.x, acc1.x);
        acc0.y = fmaf(wa, ha.y, acc0.y);  acc1.y = fmaf(wb, hb.y, acc1.y);
    }
    if (k < end) {
        int sa = g_csr[k];
        float ea = g_s2[sa] + dd;
        ea = ea > 0.f ? ea : 0.2f * ea;
        float wa = __expf(ea);
        float2 ha = __half22float2(*(const __half2*)&g_h2h[sa * 64 + lane * 2]);
        dsum0 += wa;
        acc0.x = fmaf(wa, ha.x, acc0.x);
        acc0.y = fmaf(wa, ha.y, acc0.y);
    }

    float inv = 1.f / (dsum0 + dsum1);
    float2 bb = *(const float2*)&b2[lane * 2];
    float2 o;
    o.x = fmaf(acc0.x + acc1.x, inv, bb.x);
    o.y = fmaf(acc0.y + acc1.y, inv, bb.y);
    *(float2*)&out[wid * 64 + lane * 2] = o;
}

// ---------------------------------------------------------------------------
extern "C" void kernel_launch(void* const* d_in, const int* in_sizes, int n_in,
                              void* d_out, int out_size)
{
    const float* x   = (const float*)d_in[0];
    const void*  ei  = d_in[1];
    // d_in[2] = drpt, unused at inference
    const float* W1  = (const float*)d_in[3];
    const float* a1s = (const float*)d_in[4];
    const float* a1d = (const float*)d_in[5];
    const float* b1  = (const float*)d_in[6];
    const float* W2  = (const float*)d_in[7];
    const float* a2s = (const float*)d_in[8];
    const float* a2d = (const float*)d_in[9];
    const float* b2  = (const float*)d_in[10];

    int N = in_sizes[0] / 128;
    long long E = in_sizes[1] / 2;
    int Etot = (int)E + N;

    float*  h1p;  cudaGetSymbolAddress((void**)&h1p, g_h1);
    __half* h1hp; cudaGetSymbolAddress((void**)&h1hp, g_h1h);
    float*  t1p;  cudaGetSymbolAddress((void**)&t1p, g_t1);
    __half* h2hp; cudaGetSymbolAddress((void**)&h2hp, g_h2h);
    float*  s1p;  cudaGetSymbolAddress((void**)&s1p, g_s1);
    float*  d1p;  cudaGetSymbolAddress((void**)&d1p, g_d1);
    float*  s2p;  cudaGetSymbolAddress((void**)&s2p, g_s2);
    float*  d2p;  cudaGetSymbolAddress((void**)&d2p, g_d2);

    int egrid = (Etot + 255) / 256;
    int nb = (N + SCAN_CH - 1) / SCAN_CH;

    // ---- CSR build ----
    k_zero_and_detect<<<(N + 511) / 512, 512>>>(ei, N);
    k_count<<<egrid, 256>>>(ei, E, N, Etot);
    k_scan_blk<<<nb, SCAN_CH>>>(N);
    k_scan_top<<<1, SCAN_NBMAX>>>(nb);
    k_scan_add<<<nb, SCAN_CH>>>(N);
    k_scatter<<<egrid, 256>>>(ei, E, N, Etot);

    // ---- layer 1 ---- (h1 fp32 not needed: scores fused, gather uses fp16)
    k_gemm128<128, 4><<<(N + 63) / 64, 256>>>(x, W1, a1s, a1d,
                                              h1p, h1hp, s1p, d1p, N, /*storeC=*/0);
    k_agg1<<<(N + 7) / 8, 256>>>(b1, N);

    // ---- layer 2 ---- (h2 fp32 never materialized; fp16 shadow + scores only)
    k_gemm128<64, 1><<<(N + 63) / 64, 256>>>(t1p, W2, a2s, a2d,
                                             h1p /*dummy, storeC=0*/, h2hp,
                                             s2p, d2p, N, /*storeC=*/0);
    k_agg2<<<(N + 7) / 8, 256>>>(b2, (float*)d_out, N);
}